// round 8
// baseline (speedup 1.0000x reference)
#include <cuda_runtime.h>
#include <cuda_fp16.h>

// WaterLevelLSTM via mma.sync.m16n8k16 (f16 -> f32), 2-term h split,
// MUFU.TANH activations. R8: 32 batch rows per warp (two m16 tiles per
// B-fragment load) -> per-SM shared-memory traffic for the W table and
// bias loads halves; tensor pipe becomes the ceiling. 1 CTA x 256 thr.

#define TSTEPS 5
#define NTH    256
#define MT     256           // batch rows per CTA (8 warps x 32)
#define ROWPAD 72            // halves per row (144B) -> ldsm conflict-free

// smem byte offsets
#define SM_WHI  0            // 256*72*2 = 36864
#define SM_A    36864        // 8 warps x 4608 (hi); lo at +36864
#define SM_ALO_REL 36864
#define SM_BC   110592       // [8 jg][4 tig][4 float4] = 2048 (bias+wih)
#define SM_WFC  112640       // 64 floats
#define SM_X    112896       // 256*5 floats = 5120
#define SM_SIZE 118016

typedef unsigned int u32;

__device__ __forceinline__ void mma16816(float* d, const u32* a, const u32* b) {
    asm volatile("mma.sync.aligned.m16n8k16.row.col.f32.f16.f16.f32 "
        "{%0,%1,%2,%3}, {%4,%5,%6,%7}, {%8,%9}, {%0,%1,%2,%3};"
        : "+f"(d[0]), "+f"(d[1]), "+f"(d[2]), "+f"(d[3])
        : "r"(a[0]), "r"(a[1]), "r"(a[2]), "r"(a[3]), "r"(b[0]), "r"(b[1]));
}
__device__ __forceinline__ void ldsm4(u32* r, u32 addr) {
    asm volatile("ldmatrix.sync.aligned.m8n8.x4.shared.b16 {%0,%1,%2,%3}, [%4];"
        : "=r"(r[0]), "=r"(r[1]), "=r"(r[2]), "=r"(r[3]) : "r"(addr));
}
__device__ __forceinline__ u32 s2u(const void* p) {
    u32 a;
    asm("{ .reg .u64 t; cvta.to.shared.u64 t, %1; cvt.u32.u64 %0, t; }"
        : "=r"(a) : "l"(p));
    return a;
}
__device__ __forceinline__ u32 packh2(float a, float b) {
    __half2 h = __floats2half2_rn(a, b);
    return *reinterpret_cast<u32*>(&h);
}
__device__ __forceinline__ void sts32(u32 addr, u32 v) {
    asm volatile("st.shared.b32 [%0], %1;" :: "r"(addr), "r"(v) : "memory");
}
// hardware tanh (MUFU.TANH): 1 MUFU op
__device__ __forceinline__ float tanh_hw(float x) {
    float r;
    asm("tanh.approx.f32 %0, %1;" : "=f"(r) : "f"(x));
    return r;
}
__device__ __forceinline__ float sigf(float x) {
    return fmaf(tanh_hw(0.5f * x), 0.5f, 0.5f);
}

__global__ __launch_bounds__(NTH, 1)
void lstm_mma_kernel(const float* __restrict__ x,
                     const float* __restrict__ W_ih,
                     const float* __restrict__ W_hh,
                     const float* __restrict__ b_ih,
                     const float* __restrict__ b_hh,
                     const float* __restrict__ W_fc,
                     const float* __restrict__ b_fc,
                     float* __restrict__ out,
                     int B)
{
    extern __shared__ char smem[];
    const u32 sb = s2u(smem);
    const int tid  = threadIdx.x;
    const int warp = tid >> 5;
    const int lane = tid & 31;
    const int gid  = lane >> 2;      // row group in m16 tile
    const int tig  = lane & 3;       // col group

    __half* whi   = reinterpret_cast<__half*>(smem + SM_WHI);
    float*  bc_s  = reinterpret_cast<float*>(smem + SM_BC);
    float*  wfc_s = reinterpret_cast<float*>(smem + SM_WFC);
    float*  x_s   = reinterpret_cast<float*>(smem + SM_X);

    // ---- prologue ----
    for (int i = tid; i < 256 * 64; i += NTH) {
        int n = i >> 6, k = i & 63;
        whi[n * ROWPAD + k] = __float2half_rn(W_hh[i]);
    }
    if (tid < 256) {
        int type = tid >> 6, j = tid & 63;
        int jg = j >> 3, tg = (j >> 1) & 3, col = j & 1;
        int base = (jg * 4 + tg) * 16 + col * 4 + type;
        bc_s[base]     = b_ih[tid] + b_hh[tid];
        bc_s[base + 8] = W_ih[tid];
    }
    if (tid < 64) wfc_s[tid] = W_fc[tid];
    {   // stage x (coalesced)
        long base = (long)blockIdx.x * MT * TSTEPS;
        for (int i = tid; i < MT * TSTEPS; i += NTH) {
            long gi = base + i;
            x_s[i] = (gi < (long)B * TSTEPS) ? x[gi] : 0.0f;
        }
    }
    __syncthreads();   // only block-wide sync

    // ---- per-thread setup: warp owns rows [warp*32, warp*32+32) ----
    const int rbase = warp * 32 + gid;       // CTA-local; rows rbase + {0,8,16,24}
    const float bfc = b_fc[0];

    const u32 a_hi = sb + SM_A + (u32)warp * 4608u;
    const u32 a_lo = a_hi + SM_ALO_REL;
    const u32 whi_b = sb + SM_WHI;
    const u32 lmoffB = (u32)((lane & 7) * (ROWPAD * 2) + (lane >> 3) * 16);
    const u32 lmoffA = (u32)((lane & 15) * (ROWPAD * 2) + (lane >> 4) * 16);

    float c[64];                 // c[mt*32 + jg*4 + p]
#pragma unroll
    for (int i = 0; i < 64; i++) c[i] = 0.0f;
    float oacc[4];
#pragma unroll
    for (int i = 0; i < 4; i++) oacc[i] = 0.0f;

#pragma unroll
    for (int s = 0; s < TSTEPS; s++) {
        float xs[4];             // xs[mt*2 + half]: rows rbase + mt*16 + half*8
#pragma unroll
        for (int q = 0; q < 4; q++)
            xs[q] = x_s[(rbase + q * 8) * TSTEPS + s];

        u32 Ahi[2][4][4], Alo[2][4][4];
        if (s > 0) {
#pragma unroll
            for (int mt = 0; mt < 2; mt++)
#pragma unroll
                for (int kc = 0; kc < 4; kc++) {
                    ldsm4(Ahi[mt][kc], a_hi + (u32)(mt * 2304 + kc * 32) + lmoffA);
                    ldsm4(Alo[mt][kc], a_lo + (u32)(mt * 2304 + kc * 32) + lmoffA);
                }
        }

#pragma unroll
        for (int jg = 0; jg < 8; jg++) {
            float D[2][4][4];
#pragma unroll
            for (int mt = 0; mt < 2; mt++)
#pragma unroll
                for (int ty = 0; ty < 4; ty++)
#pragma unroll
                    for (int p = 0; p < 4; p++) D[mt][ty][p] = 0.0f;

            if (s > 0) {
#pragma unroll
                for (int ty = 0; ty < 4; ty++) {
                    u32 rb = whi_b + (u32)((ty * 64 + jg * 8) * (ROWPAD * 2)) + lmoffB;
                    u32 bh[8];
                    ldsm4(bh + 0, rb);          // W_hi k[0,32)
                    ldsm4(bh + 4, rb + 64);     // W_hi k[32,64)
#pragma unroll
                    for (int mt = 0; mt < 2; mt++)
#pragma unroll
                        for (int kk = 0; kk < 4; kk++) {
                            mma16816(D[mt][ty], Ahi[mt][kk], bh + 2 * kk);
                            mma16816(D[mt][ty], Alo[mt][kk], bh + 2 * kk);
                        }
                }
            }

            // ---- epilogue: 8 units (2 tiles x 2 rows x 2 cols) ----
            const float4* bc = reinterpret_cast<const float4*>(bc_s)
                               + (jg * 4 + tig) * 4;
            float4 b0 = bc[0];   // bias col0 {i,f,g,o}
            float4 b1 = bc[1];   // bias col1
            float4 w0 = bc[2];   // wih  col0
            float4 w1 = bc[3];   // wih  col1
            const int cb = jg * 8 + 2 * tig;

#pragma unroll
            for (int mt = 0; mt < 2; mt++) {
                float hv[4];
#pragma unroll
                for (int p = 0; p < 4; p++) {
                    const float xv = xs[mt * 2 + (p >> 1)];
                    const bool hi = (p & 1);
                    const float4 bb = hi ? b1 : b0;
                    const float4 ww = hi ? w1 : w0;
                    float gI = D[mt][0][p] + fmaf(xv, ww.x, bb.x);
                    float gF = D[mt][1][p] + fmaf(xv, ww.y, bb.y);
                    float gG = D[mt][2][p] + fmaf(xv, ww.z, bb.z);
                    float gO = D[mt][3][p] + fmaf(xv, ww.w, bb.w);
                    float iv = sigf(gI);
                    float fv = sigf(gF);
                    float gv = tanh_hw(gG);
                    float ov = sigf(gO);
                    const int ci = mt * 32 + jg * 4 + p;
                    float cn = fmaf(fv, c[ci], iv * gv);
                    c[ci] = cn;
                    hv[p] = ov * tanh_hw(cn);
                }

                if (s < TSTEPS - 1) {
                    float h0h = __half2float(__float2half_rn(hv[0]));
                    float h1h = __half2float(__float2half_rn(hv[1]));
                    float h2h = __half2float(__float2half_rn(hv[2]));
                    float h3h = __half2float(__float2half_rn(hv[3]));
                    u32 off = (u32)(((mt * 16 + gid) * ROWPAD + cb) * 2);
                    sts32(a_hi + off,                  packh2(h0h, h1h));
                    sts32(a_hi + off + 8 * ROWPAD * 2, packh2(h2h, h3h));
                    sts32(a_lo + off,                  packh2(hv[0] - h0h, hv[1] - h1h));
                    sts32(a_lo + off + 8 * ROWPAD * 2, packh2(hv[2] - h2h, hv[3] - h3h));
                } else {
                    float2 wf = *(const float2*)(wfc_s + cb);
                    oacc[mt * 2 + 0] = fmaf(hv[0], wf.x, fmaf(hv[1], wf.y, oacc[mt * 2 + 0]));
                    oacc[mt * 2 + 1] = fmaf(hv[2], wf.x, fmaf(hv[3], wf.y, oacc[mt * 2 + 1]));
                }
            }
        }
        __syncwarp();   // h stores visible warp-wide before next ldsm
    }

    // ---- head: reduce over the 4 tig lanes sharing each row ----
#pragma unroll
    for (int q = 0; q < 4; q++) {
        float v = oacc[q];
        v += __shfl_xor_sync(0xffffffffu, v, 1);
        v += __shfl_xor_sync(0xffffffffu, v, 2);
        if (tig == 0) {
            // q = mt*2 + half -> row = rbase + mt*16 + half*8
            long g = (long)blockIdx.x * MT + rbase + (q >> 1) * 16 + (q & 1) * 8;
            if (g < B) out[g] = v + bfc;
        }
    }
}

extern "C" void kernel_launch(void* const* d_in, const int* in_sizes, int n_in,
                              void* d_out, int out_size) {
    const float* x    = (const float*)d_in[0];
    const float* W_ih = (const float*)d_in[1];
    const float* W_hh = (const float*)d_in[2];
    const float* b_ih = (const float*)d_in[3];
    const float* b_hh = (const float*)d_in[4];
    const float* W_fc = (const float*)d_in[5];
    const float* b_fc = (const float*)d_in[6];
    float* out = (float*)d_out;

    const int B = in_sizes[0] / TSTEPS;
    const int grid = (B + MT - 1) / MT;

    cudaFuncSetAttribute(lstm_mma_kernel,
                         cudaFuncAttributeMaxDynamicSharedMemorySize, SM_SIZE);
    lstm_mma_kernel<<<grid, NTH, SM_SIZE>>>(x, W_ih, W_hh, b_ih, b_hh,
                                            W_fc, b_fc, out, B);
}

// round 9
// speedup vs baseline: 1.7744x; 1.7744x over previous
#include <cuda_runtime.h>
#include <cuda_fp16.h>

// WaterLevelLSTM via mma.sync.m16n8k16 (f16 -> f32).
// R9 = R7 base (16 rows/warp, 2 CTAs/SM) + SINGLE-term h (h fp16, no lo
// split). Halves MMA count, A-ldmatrix, and h-store traffic; shortens the
// per-jg dependency chain. MUFU.TANH activations.

#define TSTEPS 5
#define NTH    256
#define MT     128
#define ROWPAD 72            // halves per row (144B) -> ldsm conflict-free

// smem byte offsets
#define SM_WHI  0            // 256*72*2 = 36864
#define SM_A    36864        // 8 warps x 2304 (h fp16 staging)
#define SM_BC   55296        // [8 jg][4 tig][4 float4] = 2048 (bias+wih)
#define SM_WFC  57344        // 64 floats
#define SM_SIZE 57600

typedef unsigned int u32;

__device__ __forceinline__ void mma16816(float* d, const u32* a, const u32* b) {
    asm volatile("mma.sync.aligned.m16n8k16.row.col.f32.f16.f16.f32 "
        "{%0,%1,%2,%3}, {%4,%5,%6,%7}, {%8,%9}, {%0,%1,%2,%3};"
        : "+f"(d[0]), "+f"(d[1]), "+f"(d[2]), "+f"(d[3])
        : "r"(a[0]), "r"(a[1]), "r"(a[2]), "r"(a[3]), "r"(b[0]), "r"(b[1]));
}
__device__ __forceinline__ void ldsm4(u32* r, u32 addr) {
    asm volatile("ldmatrix.sync.aligned.m8n8.x4.shared.b16 {%0,%1,%2,%3}, [%4];"
        : "=r"(r[0]), "=r"(r[1]), "=r"(r[2]), "=r"(r[3]) : "r"(addr));
}
__device__ __forceinline__ u32 s2u(const void* p) {
    u32 a;
    asm("{ .reg .u64 t; cvta.to.shared.u64 t, %1; cvt.u32.u64 %0, t; }"
        : "=r"(a) : "l"(p));
    return a;
}
__device__ __forceinline__ u32 packh2(float a, float b) {
    __half2 h = __floats2half2_rn(a, b);
    return *reinterpret_cast<u32*>(&h);
}
__device__ __forceinline__ void sts32(u32 addr, u32 v) {
    asm volatile("st.shared.b32 [%0], %1;" :: "r"(addr), "r"(v) : "memory");
}
// hardware tanh (MUFU.TANH): 1 MUFU op
__device__ __forceinline__ float tanh_hw(float x) {
    float r;
    asm("tanh.approx.f32 %0, %1;" : "=f"(r) : "f"(x));
    return r;
}
__device__ __forceinline__ float sigf(float x) {
    return fmaf(tanh_hw(0.5f * x), 0.5f, 0.5f);
}

__global__ __launch_bounds__(NTH, 2)
void lstm_mma_kernel(const float* __restrict__ x,
                     const float* __restrict__ W_ih,
                     const float* __restrict__ W_hh,
                     const float* __restrict__ b_ih,
                     const float* __restrict__ b_hh,
                     const float* __restrict__ W_fc,
                     const float* __restrict__ b_fc,
                     float* __restrict__ out,
                     int B)
{
    extern __shared__ char smem[];
    const u32 sb = s2u(smem);
    const int tid  = threadIdx.x;
    const int warp = tid >> 5;
    const int lane = tid & 31;
    const int gid  = lane >> 2;      // row group in warp tile
    const int tig  = lane & 3;       // col group

    __half* whi   = reinterpret_cast<__half*>(smem + SM_WHI);
    float*  bc_s  = reinterpret_cast<float*>(smem + SM_BC);
    float*  wfc_s = reinterpret_cast<float*>(smem + SM_WFC);

    // ---- prologue: W_hh -> fp16 table; pack bias/wih by (jg,tig,col,type) ----
    for (int i = tid; i < 256 * 64; i += NTH) {
        int n = i >> 6, k = i & 63;
        whi[n * ROWPAD + k] = __float2half_rn(W_hh[i]);
    }
    if (tid < 256) {
        int type = tid >> 6, j = tid & 63;
        int jg = j >> 3, tg = (j >> 1) & 3, col = j & 1;
        int base = (jg * 4 + tg) * 16 + col * 4 + type;
        bc_s[base]     = b_ih[tid] + b_hh[tid];
        bc_s[base + 8] = W_ih[tid];
    }
    if (tid < 64) wfc_s[tid] = W_fc[tid];
    __syncthreads();   // only block-wide sync

    // ---- per-thread setup ----
    const int row0 = warp * 16 + gid;
    const int row1 = row0 + 8;
    const long g0 = (long)blockIdx.x * MT + row0;
    const long g1 = (long)blockIdx.x * MT + row1;
    const bool v0 = g0 < B, v1 = g1 < B;
    const float bfc = b_fc[0];

    float xv0[TSTEPS], xv1[TSTEPS];
#pragma unroll
    for (int s = 0; s < TSTEPS; s++) {
        xv0[s] = v0 ? __ldg(x + g0 * TSTEPS + s) : 0.0f;
        xv1[s] = v1 ? __ldg(x + g1 * TSTEPS + s) : 0.0f;
    }

    const u32 a_hi = sb + SM_A + (u32)warp * 2304u;
    const u32 whi_b = sb + SM_WHI;
    const u32 lmoffB = (u32)((lane & 7) * (ROWPAD * 2) + (lane >> 3) * 16);
    const u32 lmoffA = (u32)((lane & 15) * (ROWPAD * 2) + (lane >> 4) * 16);

    float c[32];
#pragma unroll
    for (int i = 0; i < 32; i++) c[i] = 0.0f;
    float oacc0 = 0.0f, oacc1 = 0.0f;

#pragma unroll
    for (int s = 0; s < TSTEPS; s++) {
        u32 Ahi[4][4];
        if (s > 0) {
#pragma unroll
            for (int kc = 0; kc < 4; kc++)
                ldsm4(Ahi[kc], a_hi + (u32)kc * 32u + lmoffA);
        }
        const float xs0 = xv0[s], xs1 = xv1[s];

#pragma unroll
        for (int jg = 0; jg < 8; jg++) {
            float D[4][4];
#pragma unroll
            for (int ty = 0; ty < 4; ty++)
#pragma unroll
                for (int p = 0; p < 4; p++) D[ty][p] = 0.0f;

            if (s > 0) {
#pragma unroll
                for (int ty = 0; ty < 4; ty++) {
                    u32 rb = whi_b + (u32)((ty * 64 + jg * 8) * (ROWPAD * 2)) + lmoffB;
                    u32 bh[8];
                    ldsm4(bh + 0, rb);          // W_hi k[0,32)
                    ldsm4(bh + 4, rb + 64);     // W_hi k[32,64)
#pragma unroll
                    for (int kk = 0; kk < 4; kk++)
                        mma16816(D[ty], Ahi[kk], bh + 2 * kk);
                }
            }

            // ---- epilogue: 4 units (2 rows x 2 cols) ----
            const float4* bc = reinterpret_cast<const float4*>(bc_s)
                               + (jg * 4 + tig) * 4;
            float4 b0 = bc[0];   // bias col0 {i,f,g,o}
            float4 b1 = bc[1];   // bias col1
            float4 w0 = bc[2];   // wih  col0
            float4 w1 = bc[3];   // wih  col1

            float hv[4];
#pragma unroll
            for (int p = 0; p < 4; p++) {
                const float xs = (p < 2) ? xs0 : xs1;
                const bool hi = (p & 1);
                const float4 bb = hi ? b1 : b0;
                const float4 ww = hi ? w1 : w0;
                float gI = D[0][p] + fmaf(xs, ww.x, bb.x);
                float gF = D[1][p] + fmaf(xs, ww.y, bb.y);
                float gG = D[2][p] + fmaf(xs, ww.z, bb.z);
                float gO = D[3][p] + fmaf(xs, ww.w, bb.w);
                float iv = sigf(gI);
                float fv = sigf(gF);
                float gv = tanh_hw(gG);
                float ov = sigf(gO);
                float cn = fmaf(fv, c[jg * 4 + p], iv * gv);
                c[jg * 4 + p] = cn;
                hv[p] = ov * tanh_hw(cn);
            }

            if (s < TSTEPS - 1) {
                // stage new h (fp16, single term) for next step's A
                const int cb = jg * 8 + 2 * tig;
                u32 off = (u32)((gid * ROWPAD + cb) * 2);
                sts32(a_hi + off,                  packh2(hv[0], hv[1]));
                sts32(a_hi + off + 8 * ROWPAD * 2, packh2(hv[2], hv[3]));
            } else {
                const int cb = jg * 8 + 2 * tig;
                float2 wf = *(const float2*)(wfc_s + cb);
                oacc0 = fmaf(hv[0], wf.x, fmaf(hv[1], wf.y, oacc0));
                oacc1 = fmaf(hv[2], wf.x, fmaf(hv[3], wf.y, oacc1));
            }
        }
        __syncwarp();   // h stores visible warp-wide before next ldsm
    }

    // ---- head: reduce over the 4 tig lanes sharing each row ----
    oacc0 += __shfl_xor_sync(0xffffffffu, oacc0, 1);
    oacc0 += __shfl_xor_sync(0xffffffffu, oacc0, 2);
    oacc1 += __shfl_xor_sync(0xffffffffu, oacc1, 1);
    oacc1 += __shfl_xor_sync(0xffffffffu, oacc1, 2);
    if (tig == 0) {
        if (v0) out[g0] = oacc0 + bfc;
        if (v1) out[g1] = oacc1 + bfc;
    }
}

extern "C" void kernel_launch(void* const* d_in, const int* in_sizes, int n_in,
                              void* d_out, int out_size) {
    const float* x    = (const float*)d_in[0];
    const float* W_ih = (const float*)d_in[1];
    const float* W_hh = (const float*)d_in[2];
    const float* b_ih = (const float*)d_in[3];
    const float* b_hh = (const float*)d_in[4];
    const float* W_fc = (const float*)d_in[5];
    const float* b_fc = (const float*)d_in[6];
    float* out = (float*)d_out;

    const int B = in_sizes[0] / TSTEPS;
    const int grid = (B + MT - 1) / MT;

    cudaFuncSetAttribute(lstm_mma_kernel,
                         cudaFuncAttributeMaxDynamicSharedMemorySize, SM_SIZE);
    lstm_mma_kernel<<<grid, NTH, SM_SIZE>>>(x, W_ih, W_hh, b_ih, b_hh,
                                            W_fc, b_fc, out, B);
}